// round 4
// baseline (speedup 1.0000x reference)
#include <cuda_runtime.h>
#include <math.h>

// Multilinear form tensor: z = sum_p T[p0,p1,p2,p3] * prod_i (1, cos xi, sin xi)[pi]
// Packed as float4 per (p0,p1,p2): (T[...,0], T[...,1], T[...,2], 0)
__device__ float4 g_T4[27];

// Scratch: per-block circuit expectation values, (4096 images x 196 blocks)
__device__ float g_z[4096 * 196];

// ---------------------------------------------------------------------------
// Precompute kernel (unchanged from R1, verified): build U, M = U^T Z0 U, then
// basis-change pair indices -> (1, cos, sin) coefficient tensor T (27 float4).
// ---------------------------------------------------------------------------
__global__ void precompute_T(const float* __restrict__ qw) {
    __shared__ float U[16][16];
    __shared__ float Msh[16][16];
    __shared__ float bufA[256];
    __shared__ float bufB[256];
    __shared__ float qws[8];
    const int t = threadIdx.x;
    if (t < 8) qws[t] = qw[t];
    __syncthreads();

    if (t < 16) {
        float st[16];
#pragma unroll
        for (int k = 0; k < 16; k++) st[k] = (k == t) ? 1.f : 0.f;
#pragma unroll
        for (int l = 0; l < 2; l++) {
#pragma unroll
            for (int w = 0; w < 4; w++) {
                float th = qws[l * 4 + w];
                float c, s;
                sincosf(0.5f * th, &s, &c);
                const int m = 1 << (3 - w);
#pragma unroll
                for (int k = 0; k < 16; k++) {
                    if (!(k & m)) {
                        float s0 = st[k], s1 = st[k | m];
                        st[k]     = c * s0 - s * s1;
                        st[k | m] = s * s0 + c * s1;
                    }
                }
            }
            const int ctrl[4] = {0, 1, 2, 3};
            const int targ[4] = {1, 2, 3, 0};
#pragma unroll
            for (int e = 0; e < 4; e++) {
                const int mc = 1 << (3 - ctrl[e]);
                const int mt = 1 << (3 - targ[e]);
#pragma unroll
                for (int k = 0; k < 16; k++) {
                    if ((k & mc) && !(k & mt)) {
                        float tmp = st[k]; st[k] = st[k | mt]; st[k | mt] = tmp;
                    }
                }
            }
        }
#pragma unroll
        for (int k = 0; k < 16; k++) U[k][t] = st[k];
    }
    __syncthreads();

    for (int e = t; e < 256; e += blockDim.x) {
        const int a = e >> 4, b = e & 15;
        float acc = 0.f;
#pragma unroll
        for (int k = 0; k < 16; k++) {
            float sgn = (k & 8) ? -1.f : 1.f;
            acc += sgn * U[k][a] * U[k][b];
        }
        Msh[a][b] = acc;
    }
    __syncthreads();

    for (int e = t; e < 256; e += blockDim.x) {
        const int j3 = e & 3, j2 = (e >> 2) & 3, j1 = (e >> 4) & 3, j0 = (e >> 6) & 3;
        const int a = (j0 >> 1) * 8 + (j1 >> 1) * 4 + (j2 >> 1) * 2 + (j3 >> 1);
        const int b = (j0 & 1) * 8 + (j1 & 1) * 4 + (j2 & 1) * 2 + (j3 & 1);
        bufA[e] = Msh[a][b];
    }
    __syncthreads();

    for (int e = t; e < 192; e += blockDim.x) {
        const int p = e >> 6, r = e & 63;
        float x0 = bufA[r], x1 = bufA[64 + r], x2 = bufA[128 + r], x3 = bufA[192 + r];
        bufB[e] = (p == 0) ? 0.5f * (x0 + x3) : (p == 1) ? 0.5f * (x0 - x3) : 0.5f * (x1 + x2);
    }
    __syncthreads();
    for (int e = t; e < 144; e += blockDim.x) {
        const int q = e >> 4, r = e & 15;
        const int p0 = q / 3, p1 = q % 3;
        const float* in = &bufB[p0 * 64 + r];
        float x0 = in[0], x1 = in[16], x2 = in[32], x3 = in[48];
        bufA[e] = (p1 == 0) ? 0.5f * (x0 + x3) : (p1 == 1) ? 0.5f * (x0 - x3) : 0.5f * (x1 + x2);
    }
    __syncthreads();
    for (int e = t; e < 108; e += blockDim.x) {
        const int qq = e >> 2, j3 = e & 3;
        const int q = qq / 3, p2 = qq % 3;
        const float* in = &bufA[q * 16 + j3];
        float x0 = in[0], x1 = in[4], x2 = in[8], x3 = in[12];
        bufB[e] = (p2 == 0) ? 0.5f * (x0 + x3) : (p2 == 1) ? 0.5f * (x0 - x3) : 0.5f * (x1 + x2);
    }
    __syncthreads();
    if (t < 27) {
        const float* in = &bufB[t * 4];
        float x0 = in[0], x1 = in[1], x2 = in[2], x3 = in[3];
        g_T4[t] = make_float4(0.5f * (x0 + x3), 0.5f * (x0 - x3), 0.5f * (x1 + x2), 0.f);
    }
}

// ---------------------------------------------------------------------------
// Circuit kernel: one thread = one 2x2 block for TWO images (T loads amortized).
// No syncthreads, no smem. Grid = B/2, block = 224 (196 active).
// ---------------------------------------------------------------------------
__global__ __launch_bounds__(224) void circuit_kernel(const float* __restrict__ x) {
    const int t = threadIdx.x;
    if (t >= 196) return;
    const int imgA = blockIdx.x * 2;

    const int r = t / 14, c = t % 14;
    const float* pA = x + (size_t)imgA * 784 + r * 56 + c * 2;
    const float* pB = pA + 784;
    // 8B-aligned float2 loads (all offsets even)
    const float2 A01 = *(const float2*)pA;
    const float2 A23 = *(const float2*)(pA + 28);
    const float2 B01 = *(const float2*)pB;
    const float2 B23 = *(const float2*)(pB + 28);

    float ca0, sa0, ca1, sa1, ca2, sa2, ca3, sa3;
    float cb0, sb0, cb1, sb1, cb2, sb2, cb3, sb3;
    __sincosf(A01.x, &sa0, &ca0);
    __sincosf(A01.y, &sa1, &ca1);
    __sincosf(A23.x, &sa2, &ca2);
    __sincosf(A23.y, &sa3, &ca3);
    __sincosf(B01.x, &sb0, &cb0);
    __sincosf(B01.y, &sb1, &cb1);
    __sincosf(B23.x, &sb2, &cb2);
    __sincosf(B23.y, &sb3, &cb3);

    float BA[9], BB[9];
#pragma unroll
    for (int u = 0; u < 9; u++) {
        const float4 t0 = __ldg(&g_T4[u * 3 + 0]);
        const float4 t1 = __ldg(&g_T4[u * 3 + 1]);
        const float4 t2 = __ldg(&g_T4[u * 3 + 2]);
        // image A: contract wire3 then wire2
        float aA = fmaf(t0.z, sa3, fmaf(t0.y, ca3, t0.x));
        float bA = fmaf(t1.z, sa3, fmaf(t1.y, ca3, t1.x));
        float dA = fmaf(t2.z, sa3, fmaf(t2.y, ca3, t2.x));
        BA[u] = fmaf(dA, sa2, fmaf(bA, ca2, aA));
        // image B
        float aB = fmaf(t0.z, sb3, fmaf(t0.y, cb3, t0.x));
        float bB = fmaf(t1.z, sb3, fmaf(t1.y, cb3, t1.x));
        float dB = fmaf(t2.z, sb3, fmaf(t2.y, cb3, t2.x));
        BB[u] = fmaf(dB, sb2, fmaf(bB, cb2, aB));
    }
    {
        float C0 = fmaf(BA[2], sa1, fmaf(BA[1], ca1, BA[0]));
        float C1 = fmaf(BA[5], sa1, fmaf(BA[4], ca1, BA[3]));
        float C2 = fmaf(BA[8], sa1, fmaf(BA[7], ca1, BA[6]));
        g_z[(size_t)imgA * 196 + t] = fmaf(C2, sa0, fmaf(C1, ca0, C0));
    }
    {
        float C0 = fmaf(BB[2], sb1, fmaf(BB[1], cb1, BB[0]));
        float C1 = fmaf(BB[5], sb1, fmaf(BB[4], cb1, BB[3]));
        float C2 = fmaf(BB[8], sb1, fmaf(BB[7], cb1, BB[6]));
        g_z[(size_t)(imgA + 1) * 196 + t] = fmaf(C2, sb0, fmaf(C1, cb0, C0));
    }
}

// ---------------------------------------------------------------------------
// MLP kernel: 32 images per CTA, 256 threads.
//   GEMM mapping: warp w -> j-group {4w..4w+3} (W1 zero-padded to 32 cols),
//                 lane  -> image. Per k: 1 conflict-free LDS (z, pitch 197)
//                 + 1 broadcast LDS.128 (W1) + 4 FMA. No split-K.
// ---------------------------------------------------------------------------
__global__ __launch_bounds__(256) void mlp_kernel(
    const float* __restrict__ W1, const float* __restrict__ b1,
    const float* __restrict__ W2, const float* __restrict__ b2,
    float* __restrict__ out)
{
    __shared__ float sz[32 * 197];           // z tile, pitch 197 (conflict-free)
    __shared__ __align__(16) float sw1[196 * 32];  // W1 padded to 32 cols
    __shared__ float sh[32 * 33];            // hidden activations, pitch 33
    __shared__ float sb1[32];
    __shared__ float sw2[60];
    __shared__ float sb2[2];

    const int t = threadIdx.x;
    const int img0 = blockIdx.x * 32;

    // Stage z tile: 32*196 floats = 1568 float4 (each image row is 784B, 16B-divisible)
    const float4* zsrc = (const float4*)(g_z + (size_t)img0 * 196);
    for (int e = t; e < 1568; e += 256) {
        float4 v = zsrc[e];
        int img = e / 49;
        int k4 = e - img * 49;
        float* d = &sz[img * 197 + k4 * 4];
        d[0] = v.x; d[1] = v.y; d[2] = v.z; d[3] = v.w;
    }
    // Stage W1 (196x30) into padded 196x32
    for (int e = t; e < 5880; e += 256) {
        int k = e / 30;
        int j = e - k * 30;
        sw1[k * 32 + j] = W1[e];
    }
    for (int k = t; k < 196; k += 256) {
        sw1[k * 32 + 30] = 0.f;
        sw1[k * 32 + 31] = 0.f;
    }
    if (t < 32) sb1[t] = (t < 30) ? b1[t] : 0.f;
    if (t >= 32 && t < 92) sw2[t - 32] = W2[t - 32];
    if (t >= 92 && t < 94) sb2[t - 92] = b2[t - 92];
    __syncthreads();

    // GEMM: h[lane][4w..4w+3]
    const int lane = t & 31, w = t >> 5;
    float acc0 = 0.f, acc1 = 0.f, acc2 = 0.f, acc3 = 0.f;
    const float* zp = &sz[lane * 197];
    const float4* wp = (const float4*)&sw1[w * 4];   // stride 8 float4 per k
#pragma unroll 7
    for (int k = 0; k < 196; k++) {
        float zk = zp[k];
        float4 wv = wp[k * 8];
        acc0 = fmaf(zk, wv.x, acc0);
        acc1 = fmaf(zk, wv.y, acc1);
        acc2 = fmaf(zk, wv.z, acc2);
        acc3 = fmaf(zk, wv.w, acc3);
    }
    const int j = w * 4;
    float* hp = &sh[lane * 33 + j];
    hp[0] = fmaxf(acc0 + sb1[j + 0], 0.f);
    hp[1] = fmaxf(acc1 + sb1[j + 1], 0.f);
    hp[2] = fmaxf(acc2 + sb1[j + 2], 0.f);
    hp[3] = fmaxf(acc3 + sb1[j + 3], 0.f);
    __syncthreads();

    // Final layer: 64 threads, coalesced out
    if (t < 64) {
        const int img = t >> 1, o = t & 1;
        float a = sb2[o];
        const float* hrow = &sh[img * 33];
#pragma unroll
        for (int j2 = 0; j2 < 30; j2++)
            a = fmaf(hrow[j2], sw2[j2 * 2 + o], a);
        out[(size_t)(img0 + img) * 2 + o] = a;
    }
}

extern "C" void kernel_launch(void* const* d_in, const int* in_sizes, int n_in,
                              void* d_out, int out_size) {
    const float* x  = (const float*)d_in[0];   // (B, 784)
    const float* qw = (const float*)d_in[1];   // (2, 4)
    const float* W1 = (const float*)d_in[2];   // (196, 30)
    const float* b1 = (const float*)d_in[3];   // (30,)
    const float* W2 = (const float*)d_in[4];   // (30, 2)
    const float* b2 = (const float*)d_in[5];   // (2,)
    float* out = (float*)d_out;                // (B, 2)

    const int B = in_sizes[0] / 784;           // 4096

    precompute_T<<<1, 128>>>(qw);
    circuit_kernel<<<B / 2, 224>>>(x);
    mlp_kernel<<<B / 32, 256>>>(W1, b1, W2, b2, out);
}